// round 13
// baseline (speedup 1.0000x reference)
#include <cuda_runtime.h>
#include <cuda_bf16.h>
#include <cuda_fp16.h>
#include <cstdint>
#include <math.h>

#define BB 4
#define TT 4096
#define EE 1024
#define DD 64
#define MM (BB*TT)

// ---------------------------------------------------------------------------
// Device scratch.  Q, K: single fp16. V: single fp16, transposed.
// ---------------------------------------------------------------------------
__device__ __half g_qh [MM*DD];
__device__ __half g_kh [MM*DD];
__device__ __half g_vth[MM*DD];

// W: single fp16, transposed (rows n = mat*64+d, 64 k per row), SW128/chunk
#define WCHUNK_BYTES (192*128)
__device__ unsigned char g_wh[16*WCHUNK_BYTES];

// X: single fp16, pre-swizzled [row][16 k-chunks][128 bytes]
__device__ unsigned char g_xh[(size_t)MM*16*128];

// ---------------------------------------------------------------------------
// Helpers
// ---------------------------------------------------------------------------
#define DEVINL __device__ __forceinline__

DEVINL uint32_t smem_u32(const void* p) {
    uint32_t a;
    asm("{ .reg .u64 t; cvta.to.shared.u64 t, %1; cvt.u32.u64 %0, t; }"
        : "=r"(a) : "l"(p));
    return a;
}

#define SWZ128(o) ((o) ^ (((o) >> 3) & 0x70))

#define CP_ASYNC16(dst, src) \
    asm volatile("cp.async.cg.shared.global [%0], [%1], 16;" \
                 :: "r"(dst), "l"(src) : "memory")
#define CP_COMMIT() asm volatile("cp.async.commit_group;" ::: "memory")
#define CP_WAIT0()  asm volatile("cp.async.wait_group 0;"  ::: "memory")

DEVINL uint32_t pack_h2(__half a, __half b) {
    return (uint32_t)__half_as_ushort(a) |
           ((uint32_t)__half_as_ushort(b) << 16);
}

DEVINL void ldsm_x4(uint32_t r[4], uint32_t addr) {
    asm volatile("ldmatrix.sync.aligned.m8n8.x4.shared.b16 {%0,%1,%2,%3}, [%4];"
        : "=r"(r[0]), "=r"(r[1]), "=r"(r[2]), "=r"(r[3]) : "r"(addr));
}
DEVINL void ldsm_x2(uint32_t r[2], uint32_t addr) {
    asm volatile("ldmatrix.sync.aligned.m8n8.x2.shared.b16 {%0,%1}, [%2];"
        : "=r"(r[0]), "=r"(r[1]) : "r"(addr));
}
DEVINL void mma16816h(float c[4], const uint32_t a[4], const uint32_t b[2]) {
    asm volatile(
        "mma.sync.aligned.m16n8k16.row.col.f32.f16.f16.f32 "
        "{%0,%1,%2,%3}, {%4,%5,%6,%7}, {%8,%9}, {%0,%1,%2,%3};"
        : "+f"(c[0]), "+f"(c[1]), "+f"(c[2]), "+f"(c[3])
        : "r"(a[0]), "r"(a[1]), "r"(a[2]), "r"(a[3]), "r"(b[0]), "r"(b[1]));
}

// ---------------------------------------------------------------------------
// Merged prep: blocks < 8192 round X to fp16; rest W (single fp16, transposed).
// ---------------------------------------------------------------------------
__global__ __launch_bounds__(256) void prep(
    const float* __restrict__ X,
    const float* __restrict__ Wq, const float* __restrict__ Wk,
    const float* __restrict__ Wv)
{
    if (blockIdx.x < 8192) {
        const int u = blockIdx.x * 256 + threadIdx.x;
        const int row  = u >> 7;
        const int unit = u & 127;
        const int c    = unit >> 3;
        const int col8 = unit & 7;
        const float4 a = *(const float4*)&X[(size_t)row * EE + c * 64 + col8 * 8];
        const float4 b = *(const float4*)&X[(size_t)row * EE + c * 64 + col8 * 8 + 4];
        uint4 hh = make_uint4(
            pack_h2(__float2half_rn(a.x), __float2half_rn(a.y)),
            pack_h2(__float2half_rn(a.z), __float2half_rn(a.w)),
            pack_h2(__float2half_rn(b.x), __float2half_rn(b.y)),
            pack_h2(__float2half_rn(b.z), __float2half_rn(b.w)));
        size_t off = (((size_t)row * 16 + c) << 7)
                   + ((((uint32_t)col8 * 16) ^ ((uint32_t)(row & 7) << 4)));
        *(uint4*)(g_xh + off) = hh;
    } else {
        const int c = blockIdx.x - 8192;
        for (int it = threadIdx.x; it < 1536; it += 256) {
            int n = it % 192;
            int g = it / 192;
            int mat = n >> 6, d = n & 63;
            const float* Wm = (mat == 0) ? Wq : (mat == 1) ? Wk : Wv;
            int kk0 = g * 8;
            uint32_t hi[4];
#pragma unroll
            for (int j = 0; j < 4; j++) {
                __half h0 = __float2half_rn(Wm[(size_t)(c*64 + kk0 + 2*j    ) * 64 + d]);
                __half h1 = __float2half_rn(Wm[(size_t)(c*64 + kk0 + 2*j + 1) * 64 + d]);
                hi[j] = pack_h2(h0, h1);
            }
            uint32_t sw = SWZ128((uint32_t)n * 128 + (uint32_t)kk0 * 2);
            *(uint4*)(g_wh + (size_t)c * WCHUNK_BYTES + sw) = make_uint4(hi[0], hi[1], hi[2], hi[3]);
        }
    }
}

// ---------------------------------------------------------------------------
// QKV via mma.sync, pure fp16. Now 2 CTAs/SM (regs capped, smem 64KB pair).
// ---------------------------------------------------------------------------
#define QB_A    0
#define QB_B    8192
#define QB_STRIDE 32768
#define QKV_SMEM (2*QB_STRIDE)   // 65536

__global__ __launch_bounds__(256, 2) void qkv_mma(
    const float* __restrict__ bq, const float* __restrict__ bk,
    const float* __restrict__ bv)
{
    extern __shared__ __align__(1024) unsigned char sm[];
    const uint32_t sb = smem_u32(sm);
    const int tid  = threadIdx.x;
    const int warp = tid >> 5;
    const int lane = tid & 31;
    const int m0   = blockIdx.x * 64;
    const int wbase = warp * 24;

    const int rA = (lane & 7) | (((lane >> 3) & 1) << 3);
    const int uA = lane >> 4;
    const int rB = lane & 7;
    const int uB = (lane >> 3) & 1;
    const uint32_t swA = (uint32_t)(rA & 7) << 4;
    const uint32_t swB = (uint32_t)(rB & 7) << 4;

    float acc[4][3][4];
#pragma unroll
    for (int mt = 0; mt < 4; mt++)
#pragma unroll
        for (int nt = 0; nt < 3; nt++)
#pragma unroll
            for (int i = 0; i < 4; i++) acc[mt][nt][i] = 0.f;

    {
#pragma unroll
        for (int j = 0; j < 6; j++) {
            int f = tid + 256 * j;
            CP_ASYNC16(sb + QB_B + f * 16, g_wh + (size_t)f * 16);
        }
#pragma unroll
        for (int i = 0; i < 2; i++) {
            int w = tid + 256 * i;
            size_t src = (((size_t)(m0 + (w >> 3)) * 16) << 7) + (w & 7) * 16;
            CP_ASYNC16(sb + QB_A + (uint32_t)w * 16, g_xh + src);
        }
        CP_COMMIT();
        CP_WAIT0();
        __syncthreads();
    }

    for (int c = 0; c < 16; c++) {
        const uint32_t bufc = sb + (uint32_t)(c & 1) * QB_STRIDE;
        const uint32_t bufn = sb + (uint32_t)((c + 1) & 1) * QB_STRIDE;
        const bool hasNext = (c < 15);

        if (hasNext) {
            const unsigned char* wh = g_wh + (size_t)(c + 1) * WCHUNK_BYTES;
#pragma unroll
            for (int j = 0; j < 6; j++) {
                int f = tid + 256 * j;
                CP_ASYNC16(bufn + QB_B + f * 16, wh + (size_t)f * 16);
            }
#pragma unroll
            for (int i = 0; i < 2; i++) {
                int w = tid + 256 * i;
                size_t src = (((size_t)(m0 + (w >> 3)) * 16 + (c + 1)) << 7) + (w & 7) * 16;
                CP_ASYNC16(bufn + QB_A + (uint32_t)w * 16, g_xh + src);
            }
            CP_COMMIT();
        }

#pragma unroll
        for (int kk = 0; kk < 4; kk++) {
            uint32_t ah[4][4];
#pragma unroll
            for (int mt = 0; mt < 4; mt++) {
                uint32_t ra = bufc + QB_A + (uint32_t)(16*mt + rA) * 128
                            + (((uint32_t)(2*kk + uA) * 16) ^ swA);
                ldsm_x4(ah[mt], ra);
            }
            uint32_t bh[3][2];
#pragma unroll
            for (int nt = 0; nt < 3; nt++) {
                uint32_t rb = bufc + QB_B + (uint32_t)(wbase + 8*nt + rB) * 128
                            + (((uint32_t)(2*kk + uB) * 16) ^ swB);
                ldsm_x2(bh[nt], rb);
            }
#pragma unroll
            for (int mt = 0; mt < 4; mt++)
#pragma unroll
                for (int nt = 0; nt < 3; nt++)
                    mma16816h(acc[mt][nt], ah[mt], bh[nt]);
        }

        CP_WAIT0();
        __syncthreads();
    }

    const int gid = lane >> 2, tig = lane & 3;
#pragma unroll
    for (int mt = 0; mt < 4; mt++) {
#pragma unroll
        for (int nt = 0; nt < 3; nt++) {
            const int col0 = wbase + 8 * nt;
            const int mat  = col0 >> 6;
            const int d0   = (col0 & 63) + 2 * tig;
            const float* bp = (mat == 0) ? bq : (mat == 1) ? bk : bv;
            const float b0v = bp[d0], b1v = bp[d0 + 1];
            const int row0 = m0 + 16 * mt + gid;
            float v00 = acc[mt][nt][0] + b0v, v01 = acc[mt][nt][1] + b1v;
            float v10 = acc[mt][nt][2] + b0v, v11 = acc[mt][nt][3] + b1v;
            if (mat == 0) {
                v00 *= 0.125f; v01 *= 0.125f; v10 *= 0.125f; v11 *= 0.125f;
                *(uint32_t*)&g_qh[(size_t)row0 * DD + d0] =
                    pack_h2(__float2half_rn(v00), __float2half_rn(v01));
                *(uint32_t*)&g_qh[(size_t)(row0 + 8) * DD + d0] =
                    pack_h2(__float2half_rn(v10), __float2half_rn(v11));
            } else if (mat == 1) {
                *(uint32_t*)&g_kh[(size_t)row0 * DD + d0] =
                    pack_h2(__float2half_rn(v00), __float2half_rn(v01));
                *(uint32_t*)&g_kh[(size_t)(row0 + 8) * DD + d0] =
                    pack_h2(__float2half_rn(v10), __float2half_rn(v11));
            } else {
                const int bb = row0 >> 12, t = row0 & 4095;
                size_t r0o = ((size_t)bb * 64 + d0) * TT + t;
                size_t r1o = ((size_t)bb * 64 + d0 + 1) * TT + t;
                g_vth[r0o]     = __float2half_rn(v00);
                g_vth[r1o]     = __float2half_rn(v01);
                g_vth[r0o + 8] = __float2half_rn(v10);
                g_vth[r1o + 8] = __float2half_rn(v11);
            }
        }
    }
}

// ---------------------------------------------------------------------------
// Flash attention, pure fp16. 128-thread CTAs (4 warps), each processing
// q-tile pair (qp, 63-qp) SEQUENTIALLY -> 65 kv-tiles/CTA, 40KB smem,
// multiple CTAs/SM for cross-CTA latency hiding. Grid (64, B).
// Layout: Q 8K @0, K stages @8192 (2x8K), V stages @24576 (2x8K).
// ---------------------------------------------------------------------------
#define ATTN_SMEM 40960

DEVINL void stage_kv(uint32_t kdst, uint32_t vdst, int tid, int b, int t0) {
#pragma unroll
    for (int i = 0; i < 8; i++) {
        int u = tid + 128 * i;
        int mat = u >> 9, w = u & 511, r = w >> 3, cu = w & 7;
        const __half* src = mat
            ? g_vth + ((size_t)b * DD + r) * TT + t0 + cu * 8
            : g_kh  + (size_t)(b * TT + t0 + r) * DD + cu * 8;
        uint32_t dst = (mat ? vdst : kdst) + (uint32_t)r * 128
                     + (((uint32_t)cu * 16) ^ ((uint32_t)(r & 7) << 4));
        CP_ASYNC16(dst, src);
    }
}

__global__ __launch_bounds__(128, 2) void attn_mma(float* __restrict__ out)
{
    extern __shared__ __align__(1024) unsigned char sm[];
    const uint32_t sb = smem_u32(sm);
    const int tid  = threadIdx.x;
    const int wh   = tid >> 5;
    const int lane = tid & 31;
    const int b    = blockIdx.y;
    const int qp   = blockIdx.x;

    const int gid = lane >> 2, tig = lane & 3;
    const int rA = (lane & 7) | (((lane >> 3) & 1) << 3);
    const int uA = lane >> 4;
    const int rB = lane & 7;
    const int uB = (lane >> 3) & 1;
    const uint32_t swA = (uint32_t)(rA & 7) << 4;
    const uint32_t swB = (uint32_t)(rB) << 4;

    for (int qsel = 0; qsel < 2; qsel++) {
        const int qt   = qsel ? (63 - qp) : qp;
        const int tok0 = b * TT + qt * 64;

        // previous pass fully done with smem (its kv loop consumed all stages)
        __syncthreads();

        // ---- stage Q + KV tile 0 ----
#pragma unroll
        for (int i = 0; i < 4; i++) {
            int u = tid + 128 * i;                // 0..511
            int r = u >> 3, cu = u & 7;
            const __half* src = g_qh + (size_t)(tok0 + r) * DD + cu * 8;
            uint32_t dst = sb + (uint32_t)r * 128
                         + (((uint32_t)cu * 16) ^ ((uint32_t)(r & 7) << 4));
            CP_ASYNC16(dst, src);
        }
        stage_kv(sb + 8192, sb + 24576, tid, b, 0);
        CP_COMMIT();
        CP_WAIT0();
        __syncthreads();

        uint32_t qh[4][4];
#pragma unroll
        for (int kk = 0; kk < 4; kk++) {
            uint32_t ra = sb + (uint32_t)(wh * 16 + rA) * 128
                        + (((uint32_t)(2*kk + uA) * 16) ^ swA);
            ldsm_x4(qh[kk], ra);
        }

        float oA[8][4];
#pragma unroll
        for (int nd = 0; nd < 8; nd++)
#pragma unroll
            for (int i = 0; i < 4; i++) oA[nd][i] = 0.f;
        float m0r = -3.0e38f, m1r = -3.0e38f, l0r = 0.f, l1r = 0.f;

        for (int j = 0; j <= qt; j++) {
            if (j) { CP_WAIT0(); __syncthreads(); }
            const uint32_t kbase = sb + 8192  + (uint32_t)(j & 1) * 8192;
            const uint32_t vbase = sb + 24576 + (uint32_t)(j & 1) * 8192;

            if (j < qt) {
                stage_kv(sb + 8192  + (uint32_t)((j + 1) & 1) * 8192,
                         sb + 24576 + (uint32_t)((j + 1) & 1) * 8192,
                         tid, b, (j + 1) * 64);
                CP_COMMIT();
            }

            // ---- S = Q . K^T (single-term fp16) ----
            float sA[8][4];
#pragma unroll
            for (int nt = 0; nt < 8; nt++)
#pragma unroll
                for (int i = 0; i < 4; i++) sA[nt][i] = 0.f;
#pragma unroll
            for (int kk = 0; kk < 4; kk++) {
                uint32_t bh[8][2];
#pragma unroll
                for (int nt = 0; nt < 8; nt++) {
                    uint32_t rb = kbase + (uint32_t)(nt * 8 + rB) * 128
                                + (((uint32_t)(2*kk + uB) * 16) ^ swB);
                    ldsm_x2(bh[nt], rb);
                }
#pragma unroll
                for (int nt = 0; nt < 8; nt++) mma16816h(sA[nt], qh[kk], bh[nt]);
            }

            // ---- causal mask (diagonal tile only; scale folded into q) ----
            if (j == qt) {
                const int r0 = qt * 64 + wh * 16 + gid, r1 = r0 + 8;
#pragma unroll
                for (int nt = 0; nt < 8; nt++) {
                    int c0 = j * 64 + nt * 8 + 2 * tig;
                    if (c0     > r0) sA[nt][0] = -1e30f;
                    if (c0 + 1 > r0) sA[nt][1] = -1e30f;
                    if (c0     > r1) sA[nt][2] = -1e30f;
                    if (c0 + 1 > r1) sA[nt][3] = -1e30f;
                }
            }

            // ---- online softmax ----
            float mx0 = sA[0][0], mx1 = sA[0][2];
#pragma unroll
            for (int nt = 0; nt < 8; nt++) {
                mx0 = fmaxf(mx0, fmaxf(sA[nt][0], sA[nt][1]));
                mx1 = fmaxf(mx1, fmaxf(sA[nt][2], sA[nt][3]));
            }
            mx0 = fmaxf(mx0, __shfl_xor_sync(0xffffffffu, mx0, 1));
            mx0 = fmaxf(mx0, __shfl_xor_sync(0xffffffffu, mx0, 2));
            mx1 = fmaxf(mx1, __shfl_xor_sync(0xffffffffu, mx1, 1));
            mx1 = fmaxf(mx1, __shfl_xor_sync(0xffffffffu, mx1, 2));
            float mn0 = fmaxf(m0r, mx0), mn1 = fmaxf(m1r, mx1);
            float al0 = __expf(m0r - mn0), al1 = __expf(m1r - mn1);
            float ps0 = 0.f, ps1 = 0.f;
#pragma unroll
            for (int nt = 0; nt < 8; nt++) {
                sA[nt][0] = __expf(sA[nt][0] - mn0);
                sA[nt][1] = __expf(sA[nt][1] - mn0);
                sA[nt][2] = __expf(sA[nt][2] - mn1);
                sA[nt][3] = __expf(sA[nt][3] - mn1);
                ps0 += sA[nt][0] + sA[nt][1];
                ps1 += sA[nt][2] + sA[nt][3];
            }
            ps0 += __shfl_xor_sync(0xffffffffu, ps0, 1);
            ps0 += __shfl_xor_sync(0xffffffffu, ps0, 2);
            ps1 += __shfl_xor_sync(0xffffffffu, ps1, 1);
            ps1 += __shfl_xor_sync(0xffffffffu, ps1, 2);
            l0r = l0r * al0 + ps0;  m0r = mn0;
            l1r = l1r * al1 + ps1;  m1r = mn1;
#pragma unroll
            for (int nd = 0; nd < 8; nd++) {
                oA[nd][0] *= al0; oA[nd][1] *= al0;
                oA[nd][2] *= al1; oA[nd][3] *= al1;
            }

            // ---- PV: O += round16(P) . Vh ----
#pragma unroll
            for (int kk = 0; kk < 4; kk++) {
                uint32_t ap[4];
                ap[0] = pack_h2(__float2half_rn(sA[2*kk][0]),   __float2half_rn(sA[2*kk][1]));
                ap[1] = pack_h2(__float2half_rn(sA[2*kk][2]),   __float2half_rn(sA[2*kk][3]));
                ap[2] = pack_h2(__float2half_rn(sA[2*kk+1][0]), __float2half_rn(sA[2*kk+1][1]));
                ap[3] = pack_h2(__float2half_rn(sA[2*kk+1][2]), __float2half_rn(sA[2*kk+1][3]));
                uint32_t vh[8][2];
#pragma unroll
                for (int nd = 0; nd < 8; nd++) {
                    uint32_t rv = vbase + (uint32_t)(nd * 8 + rB) * 128
                                + (((uint32_t)(2*kk + uB) * 16) ^ swB);
                    ldsm_x2(vh[nd], rv);
                }
#pragma unroll
                for (int nd = 0; nd < 8; nd++) mma16816h(oA[nd], ap, vh[nd]);
            }
        }

        // ---- epilogue for this q-tile ----
        const float inv0 = 1.f / l0r, inv1 = 1.f / l1r;
        const size_t out0 = ((size_t)b * TT + qt * 64 + wh * 16 + gid) * DD;
        const size_t out1 = out0 + 8 * DD;
#pragma unroll
        for (int nd = 0; nd < 8; nd++) {
            const int d0 = nd * 8 + 2 * tig;
            *(float2*)&out[out0 + d0] = make_float2(oA[nd][0] * inv0, oA[nd][1] * inv0);
            *(float2*)&out[out1 + d0] = make_float2(oA[nd][2] * inv1, oA[nd][3] * inv1);
        }
    }
}

// ---------------------------------------------------------------------------
extern "C" void kernel_launch(void* const* d_in, const int* in_sizes, int n_in,
                              void* d_out, int out_size)
{
    const float* X  = (const float*)d_in[0];
    const float* Wq = (const float*)d_in[1];
    const float* bq = (const float*)d_in[2];
    const float* Wk = (const float*)d_in[3];
    const float* bk = (const float*)d_in[4];
    const float* Wv = (const float*)d_in[5];
    const float* bv = (const float*)d_in[6];
    float* out = (float*)d_out;

    prep<<<8192 + 16, 256>>>(X, Wq, Wk, Wv);

    cudaFuncSetAttribute(qkv_mma, cudaFuncAttributeMaxDynamicSharedMemorySize, QKV_SMEM);
    qkv_mma<<<MM / 64, 256, QKV_SMEM>>>(bq, bk, bv);

    cudaFuncSetAttribute(attn_mma, cudaFuncAttributeMaxDynamicSharedMemorySize, ATTN_SMEM);
    attn_mma<<<dim3(64, BB), 128, ATTN_SMEM>>>(out);
}

// round 16
// speedup vs baseline: 1.0650x; 1.0650x over previous
#include <cuda_runtime.h>
#include <cuda_bf16.h>
#include <cuda_fp16.h>
#include <cstdint>
#include <math.h>

#define BB 4
#define TT 4096
#define EE 1024
#define DD 64
#define MM (BB*TT)

// ---------------------------------------------------------------------------
// Device scratch.  Q, K: single fp16. V: single fp16, transposed.
// ---------------------------------------------------------------------------
__device__ __half g_qh [MM*DD];
__device__ __half g_kh [MM*DD];
__device__ __half g_vth[MM*DD];

#define WCHUNK_BYTES (192*128)
__device__ unsigned char g_wh[16*WCHUNK_BYTES];
__device__ unsigned char g_xh[(size_t)MM*16*128];

// ---------------------------------------------------------------------------
// Helpers
// ---------------------------------------------------------------------------
#define DEVINL __device__ __forceinline__

DEVINL uint32_t smem_u32(const void* p) {
    uint32_t a;
    asm("{ .reg .u64 t; cvta.to.shared.u64 t, %1; cvt.u32.u64 %0, t; }"
        : "=r"(a) : "l"(p));
    return a;
}

#define SWZ128(o) ((o) ^ (((o) >> 3) & 0x70))

#define CP_ASYNC16(dst, src) \
    asm volatile("cp.async.cg.shared.global [%0], [%1], 16;" \
                 :: "r"(dst), "l"(src) : "memory")
#define CP_COMMIT() asm volatile("cp.async.commit_group;" ::: "memory")
#define CP_WAIT0()  asm volatile("cp.async.wait_group 0;"  ::: "memory")

#define NB_SYNC(id) asm volatile("bar.sync %0, 128;" :: "r"(id) : "memory")

DEVINL uint32_t pack_h2(__half a, __half b) {
    return (uint32_t)__half_as_ushort(a) |
           ((uint32_t)__half_as_ushort(b) << 16);
}

DEVINL void ldsm_x4(uint32_t r[4], uint32_t addr) {
    asm volatile("ldmatrix.sync.aligned.m8n8.x4.shared.b16 {%0,%1,%2,%3}, [%4];"
        : "=r"(r[0]), "=r"(r[1]), "=r"(r[2]), "=r"(r[3]) : "r"(addr));
}
DEVINL void ldsm_x2(uint32_t r[2], uint32_t addr) {
    asm volatile("ldmatrix.sync.aligned.m8n8.x2.shared.b16 {%0,%1}, [%2];"
        : "=r"(r[0]), "=r"(r[1]) : "r"(addr));
}
DEVINL void mma16816h(float c[4], const uint32_t a[4], const uint32_t b[2]) {
    asm volatile(
        "mma.sync.aligned.m16n8k16.row.col.f32.f16.f16.f32 "
        "{%0,%1,%2,%3}, {%4,%5,%6,%7}, {%8,%9}, {%0,%1,%2,%3};"
        : "+f"(c[0]), "+f"(c[1]), "+f"(c[2]), "+f"(c[3])
        : "r"(a[0]), "r"(a[1]), "r"(a[2]), "r"(a[3]), "r"(b[0]), "r"(b[1]));
}

// ---------------------------------------------------------------------------
// Merged prep (R12, verified)
// ---------------------------------------------------------------------------
__global__ __launch_bounds__(256) void prep(
    const float* __restrict__ X,
    const float* __restrict__ Wq, const float* __restrict__ Wk,
    const float* __restrict__ Wv)
{
    if (blockIdx.x < 8192) {
        const int u = blockIdx.x * 256 + threadIdx.x;
        const int row  = u >> 7;
        const int unit = u & 127;
        const int c    = unit >> 3;
        const int col8 = unit & 7;
        const float4 a = *(const float4*)&X[(size_t)row * EE + c * 64 + col8 * 8];
        const float4 b = *(const float4*)&X[(size_t)row * EE + c * 64 + col8 * 8 + 4];
        uint4 hh = make_uint4(
            pack_h2(__float2half_rn(a.x), __float2half_rn(a.y)),
            pack_h2(__float2half_rn(a.z), __float2half_rn(a.w)),
            pack_h2(__float2half_rn(b.x), __float2half_rn(b.y)),
            pack_h2(__float2half_rn(b.z), __float2half_rn(b.w)));
        size_t off = (((size_t)row * 16 + c) << 7)
                   + ((((uint32_t)col8 * 16) ^ ((uint32_t)(row & 7) << 4)));
        *(uint4*)(g_xh + off) = hh;
    } else {
        const int c = blockIdx.x - 8192;
        for (int it = threadIdx.x; it < 1536; it += 256) {
            int n = it % 192;
            int g = it / 192;
            int mat = n >> 6, d = n & 63;
            const float* Wm = (mat == 0) ? Wq : (mat == 1) ? Wk : Wv;
            int kk0 = g * 8;
            uint32_t hi[4];
#pragma unroll
            for (int j = 0; j < 4; j++) {
                __half h0 = __float2half_rn(Wm[(size_t)(c*64 + kk0 + 2*j    ) * 64 + d]);
                __half h1 = __float2half_rn(Wm[(size_t)(c*64 + kk0 + 2*j + 1) * 64 + d]);
                hi[j] = pack_h2(h0, h1);
            }
            uint32_t sw = SWZ128((uint32_t)n * 128 + (uint32_t)kk0 * 2);
            *(uint4*)(g_wh + (size_t)c * WCHUNK_BYTES + sw) = make_uint4(hi[0], hi[1], hi[2], hi[3]);
        }
    }
}

// ---------------------------------------------------------------------------
// QKV via mma.sync, pure fp16 (R12, verified)
// ---------------------------------------------------------------------------
#define QB_A    0
#define QB_B    8192
#define QB_STRIDE 32768
#define QKV_SMEM (2*QB_STRIDE)   // 65536

__global__ __launch_bounds__(256, 1) void qkv_mma(
    const float* __restrict__ bq, const float* __restrict__ bk,
    const float* __restrict__ bv)
{
    extern __shared__ __align__(1024) unsigned char sm[];
    const uint32_t sb = smem_u32(sm);
    const int tid  = threadIdx.x;
    const int warp = tid >> 5;
    const int lane = tid & 31;
    const int m0   = blockIdx.x * 64;
    const int wbase = warp * 24;

    const int rA = (lane & 7) | (((lane >> 3) & 1) << 3);
    const int uA = lane >> 4;
    const int rB = lane & 7;
    const int uB = (lane >> 3) & 1;
    const uint32_t swA = (uint32_t)(rA & 7) << 4;
    const uint32_t swB = (uint32_t)(rB & 7) << 4;

    float acc[4][3][4];
#pragma unroll
    for (int mt = 0; mt < 4; mt++)
#pragma unroll
        for (int nt = 0; nt < 3; nt++)
#pragma unroll
            for (int i = 0; i < 4; i++) acc[mt][nt][i] = 0.f;

    {
#pragma unroll
        for (int j = 0; j < 6; j++) {
            int f = tid + 256 * j;
            CP_ASYNC16(sb + QB_B + f * 16, g_wh + (size_t)f * 16);
        }
#pragma unroll
        for (int i = 0; i < 2; i++) {
            int w = tid + 256 * i;
            size_t src = (((size_t)(m0 + (w >> 3)) * 16) << 7) + (w & 7) * 16;
            CP_ASYNC16(sb + QB_A + (uint32_t)w * 16, g_xh + src);
        }
        CP_COMMIT();
        CP_WAIT0();
        __syncthreads();
    }

    for (int c = 0; c < 16; c++) {
        const uint32_t bufc = sb + (uint32_t)(c & 1) * QB_STRIDE;
        const uint32_t bufn = sb + (uint32_t)((c + 1) & 1) * QB_STRIDE;
        const bool hasNext = (c < 15);

        if (hasNext) {
            const unsigned char* wh = g_wh + (size_t)(c + 1) * WCHUNK_BYTES;
#pragma unroll
            for (int j = 0; j < 6; j++) {
                int f = tid + 256 * j;
                CP_ASYNC16(bufn + QB_B + f * 16, wh + (size_t)f * 16);
            }
#pragma unroll
            for (int i = 0; i < 2; i++) {
                int w = tid + 256 * i;
                size_t src = (((size_t)(m0 + (w >> 3)) * 16 + (c + 1)) << 7) + (w & 7) * 16;
                CP_ASYNC16(bufn + QB_A + (uint32_t)w * 16, g_xh + src);
            }
            CP_COMMIT();
        }

#pragma unroll
        for (int kk = 0; kk < 4; kk++) {
            uint32_t ah[4][4];
#pragma unroll
            for (int mt = 0; mt < 4; mt++) {
                uint32_t ra = bufc + QB_A + (uint32_t)(16*mt + rA) * 128
                            + (((uint32_t)(2*kk + uA) * 16) ^ swA);
                ldsm_x4(ah[mt], ra);
            }
            uint32_t bh[3][2];
#pragma unroll
            for (int nt = 0; nt < 3; nt++) {
                uint32_t rb = bufc + QB_B + (uint32_t)(wbase + 8*nt + rB) * 128
                            + (((uint32_t)(2*kk + uB) * 16) ^ swB);
                ldsm_x2(bh[nt], rb);
            }
#pragma unroll
            for (int mt = 0; mt < 4; mt++)
#pragma unroll
                for (int nt = 0; nt < 3; nt++)
                    mma16816h(acc[mt][nt], ah[mt], bh[nt]);
        }

        CP_WAIT0();
        __syncthreads();
    }

    const int gid = lane >> 2, tig = lane & 3;
#pragma unroll
    for (int mt = 0; mt < 4; mt++) {
#pragma unroll
        for (int nt = 0; nt < 3; nt++) {
            const int col0 = wbase + 8 * nt;
            const int mat  = col0 >> 6;
            const int d0   = (col0 & 63) + 2 * tig;
            const float* bp = (mat == 0) ? bq : (mat == 1) ? bk : bv;
            const float b0v = bp[d0], b1v = bp[d0 + 1];
            const int row0 = m0 + 16 * mt + gid;
            float v00 = acc[mt][nt][0] + b0v, v01 = acc[mt][nt][1] + b1v;
            float v10 = acc[mt][nt][2] + b0v, v11 = acc[mt][nt][3] + b1v;
            if (mat == 0) {
                v00 *= 0.125f; v01 *= 0.125f; v10 *= 0.125f; v11 *= 0.125f;
                *(uint32_t*)&g_qh[(size_t)row0 * DD + d0] =
                    pack_h2(__float2half_rn(v00), __float2half_rn(v01));
                *(uint32_t*)&g_qh[(size_t)(row0 + 8) * DD + d0] =
                    pack_h2(__float2half_rn(v10), __float2half_rn(v11));
            } else if (mat == 1) {
                *(uint32_t*)&g_kh[(size_t)row0 * DD + d0] =
                    pack_h2(__float2half_rn(v00), __float2half_rn(v01));
                *(uint32_t*)&g_kh[(size_t)(row0 + 8) * DD + d0] =
                    pack_h2(__float2half_rn(v10), __float2half_rn(v11));
            } else {
                const int bb = row0 >> 12, t = row0 & 4095;
                size_t r0o = ((size_t)bb * 64 + d0) * TT + t;
                size_t r1o = ((size_t)bb * 64 + d0 + 1) * TT + t;
                g_vth[r0o]     = __float2half_rn(v00);
                g_vth[r1o]     = __float2half_rn(v01);
                g_vth[r0o + 8] = __float2half_rn(v10);
                g_vth[r1o + 8] = __float2half_rn(v11);
            }
        }
    }
}

// ---------------------------------------------------------------------------
// Flash attention, pure fp16, delayed-PV pipeline: PV_{j-1} issues between
// the row-max chains and the exp/sum chains of softmax_j (independent MMA
// stream fills the tensor-pipe bubble). P carry = 16 regs. V = 3-ring.
// Per half: Q 8K @0, K @8192 (2x8K), V @24576 (3x8K) = 48K. Grid (32, B).
// ---------------------------------------------------------------------------
#define AH_STRIDE 49152
#define ATTN_SMEM (2*AH_STRIDE)   // 98304

DEVINL void stage_k(uint32_t dst, int htid, int b, int t0) {
#pragma unroll
    for (int i = 0; i < 4; i++) {
        int u = htid + 128 * i;                // 0..511
        int r = u >> 3, cu = u & 7;
        const __half* src = g_kh + (size_t)(b * TT + t0 + r) * DD + cu * 8;
        uint32_t d = dst + (uint32_t)r * 128
                   + (((uint32_t)cu * 16) ^ ((uint32_t)(r & 7) << 4));
        CP_ASYNC16(d, src);
    }
}
DEVINL void stage_v(uint32_t dst, int htid, int b, int t0) {
#pragma unroll
    for (int i = 0; i < 4; i++) {
        int u = htid + 128 * i;
        int r = u >> 3, cu = u & 7;
        const __half* src = g_vth + ((size_t)b * DD + r) * TT + t0 + cu * 8;
        uint32_t d = dst + (uint32_t)r * 128
                   + (((uint32_t)cu * 16) ^ ((uint32_t)(r & 7) << 4));
        CP_ASYNC16(d, src);
    }
}

// PV: O += ap . Vh (single-term)
DEVINL void pv_accum(float oA[8][4], const uint32_t ap[4][4], uint32_t vbase,
                     int rB, int uB, uint32_t swB) {
#pragma unroll
    for (int kk = 0; kk < 4; kk++) {
        uint32_t vh[8][2];
#pragma unroll
        for (int nd = 0; nd < 8; nd++) {
            uint32_t rv = vbase + (uint32_t)(nd * 8 + rB) * 128
                        + (((uint32_t)(2*kk + uB) * 16) ^ swB);
            ldsm_x2(vh[nd], rv);
        }
#pragma unroll
        for (int nd = 0; nd < 8; nd++) mma16816h(oA[nd], ap[kk], vh[nd]);
    }
}

__global__ __launch_bounds__(256, 1) void attn_mma(float* __restrict__ out)
{
    extern __shared__ __align__(1024) unsigned char sm[];
    const uint32_t sb = smem_u32(sm);
    const int tid  = threadIdx.x;
    const int warp = tid >> 5;
    const int lane = tid & 31;
    const int half = warp >> 2;
    const int wh   = warp & 3;
    const int htid = tid & 127;
    const int b    = blockIdx.y;
    const int qp   = blockIdx.x;
    const int qt   = half ? (63 - qp) : qp;
    const uint32_t hb = sb + (uint32_t)half * AH_STRIDE;
    const int tok0 = b * TT + qt * 64;
    const int nbid = half + 1;

    const int gid = lane >> 2, tig = lane & 3;
    const int rA = (lane & 7) | (((lane >> 3) & 1) << 3);
    const int uA = lane >> 4;
    const int rB = lane & 7;
    const int uB = (lane >> 3) & 1;
    const uint32_t swA = (uint32_t)(rA & 7) << 4;
    const uint32_t swB = (uint32_t)(rB) << 4;

    // ---- stage Q + K0 + V0 ----
#pragma unroll
    for (int i = 0; i < 4; i++) {
        int u = htid + 128 * i;
        int r = u >> 3, cu = u & 7;
        const __half* src = g_qh + (size_t)(tok0 + r) * DD + cu * 8;
        uint32_t dst = hb + (uint32_t)r * 128
                     + (((uint32_t)cu * 16) ^ ((uint32_t)(r & 7) << 4));
        CP_ASYNC16(dst, src);
    }
    stage_k(hb + 8192,  htid, b, 0);
    stage_v(hb + 24576, htid, b, 0);
    CP_COMMIT();
    CP_WAIT0();
    NB_SYNC(nbid);

    uint32_t qh[4][4];
#pragma unroll
    for (int kk = 0; kk < 4; kk++) {
        uint32_t ra = hb + (uint32_t)(wh * 16 + rA) * 128
                    + (((uint32_t)(2*kk + uA) * 16) ^ swA);
        ldsm_x4(qh[kk], ra);
    }

    float oA[8][4];
#pragma unroll
    for (int nd = 0; nd < 8; nd++)
#pragma unroll
        for (int i = 0; i < 4; i++) oA[nd][i] = 0.f;
    float m0r = -3.0e38f, m1r = -3.0e38f, l0r = 0.f, l1r = 0.f;
    uint32_t ap[4][4];   // carried P fragments (16 regs)
    int svN = 1;         // V prefetch ring stage for iter 0 -> (0+1)%3
    int svP = 2;         // V ring stage for PV_{j-1}; becomes (j-1)%3

    for (int j = 0; j <= qt; j++) {
        if (j) { CP_WAIT0(); NB_SYNC(nbid); }

        if (j < qt) {
            stage_k(hb + 8192  + (uint32_t)((j + 1) & 1) * 8192, htid, b, (j + 1) * 64);
            stage_v(hb + 24576 + (uint32_t)svN * 8192,           htid, b, (j + 1) * 64);
            CP_COMMIT();
        }
        const uint32_t kbase = hb + 8192 + (uint32_t)(j & 1) * 8192;

        // ---- S_j = Q . K^T (single-term fp16) ----
        float sA[8][4];
#pragma unroll
        for (int nt = 0; nt < 8; nt++)
#pragma unroll
            for (int i = 0; i < 4; i++) sA[nt][i] = 0.f;
#pragma unroll
        for (int kk = 0; kk < 4; kk++) {
            uint32_t bh[8][2];
#pragma unroll
            for (int nt = 0; nt < 8; nt++) {
                uint32_t rb = kbase + (uint32_t)(nt * 8 + rB) * 128
                            + (((uint32_t)(2*kk + uB) * 16) ^ swB);
                ldsm_x2(bh[nt], rb);
            }
#pragma unroll
            for (int nt = 0; nt < 8; nt++) mma16816h(sA[nt], qh[kk], bh[nt]);
        }

        // ---- causal mask (diagonal tile only; scale folded into q) ----
        if (j == qt) {
            const int r0 = qt * 64 + wh * 16 + gid, r1 = r0 + 8;
#pragma unroll
            for (int nt = 0; nt < 8; nt++) {
                int c0 = j * 64 + nt * 8 + 2 * tig;
                if (c0     > r0) sA[nt][0] = -1e30f;
                if (c0 + 1 > r0) sA[nt][1] = -1e30f;
                if (c0     > r1) sA[nt][2] = -1e30f;
                if (c0 + 1 > r1) sA[nt][3] = -1e30f;
            }
        }

        // ---- row max + alpha (latency chains) ----
        float mx0 = sA[0][0], mx1 = sA[0][2];
#pragma unroll
        for (int nt = 0; nt < 8; nt++) {
            mx0 = fmaxf(mx0, fmaxf(sA[nt][0], sA[nt][1]));
            mx1 = fmaxf(mx1, fmaxf(sA[nt][2], sA[nt][3]));
        }
        mx0 = fmaxf(mx0, __shfl_xor_sync(0xffffffffu, mx0, 1));
        mx0 = fmaxf(mx0, __shfl_xor_sync(0xffffffffu, mx0, 2));
        mx1 = fmaxf(mx1, __shfl_xor_sync(0xffffffffu, mx1, 1));
        mx1 = fmaxf(mx1, __shfl_xor_sync(0xffffffffu, mx1, 2));
        float mn0 = fmaxf(m0r, mx0), mn1 = fmaxf(m1r, mx1);
        float al0 = __expf(m0r - mn0), al1 = __expf(m1r - mn1);

        // ---- PV_{j-1}: independent MMA stream overlapping softmax ----
        if (j) pv_accum(oA, ap, hb + 24576 + (uint32_t)svP * 8192, rB, uB, swB);

        // ---- exp + row sums ----
        float ps0 = 0.f, ps1 = 0.f;
#pragma unroll
        for (int nt = 0; nt < 8; nt++) {
            sA[nt][0] = __expf(sA[nt][0] - mn0);
            sA[nt][1] = __expf(sA[nt][1] - mn0);
            sA[nt][2] = __expf(sA[nt][2] - mn1);
            sA[nt][3] = __expf(sA[nt][3] - mn1);
            ps0 += sA[nt][0] + sA[nt][1];
            ps1 += sA[nt][2] + sA[nt][3];
        }
        ps0 += __shfl_xor_sync(0xffffffffu, ps0, 1);
        ps0 += __shfl_xor_sync(0xffffffffu, ps0, 2);
        ps1 += __shfl_xor_sync(0xffffffffu, ps1, 1);
        ps1 += __shfl_xor_sync(0xffffffffu, ps1, 2);
        l0r = l0r * al0 + ps0;  m0r = mn0;
        l1r = l1r * al1 + ps1;  m1r = mn1;

        // ---- O rescale AFTER PV_{j-1} add:  O = (O + P_{j-1}V_{j-1})*al_j ----
#pragma unroll
        for (int nd = 0; nd < 8; nd++) {
            oA[nd][0] *= al0; oA[nd][1] *= al0;
            oA[nd][2] *= al1; oA[nd][3] *= al1;
        }

        // ---- pack P_j for next iteration ----
#pragma unroll
        for (int kk = 0; kk < 4; kk++) {
            ap[kk][0] = pack_h2(__float2half_rn(sA[2*kk][0]),   __float2half_rn(sA[2*kk][1]));
            ap[kk][1] = pack_h2(__float2half_rn(sA[2*kk][2]),   __float2half_rn(sA[2*kk][3]));
            ap[kk][2] = pack_h2(__float2half_rn(sA[2*kk+1][0]), __float2half_rn(sA[2*kk+1][1]));
            ap[kk][3] = pack_h2(__float2half_rn(sA[2*kk+1][2]), __float2half_rn(sA[2*kk+1][3]));
        }

        svN = (svN == 2) ? 0 : svN + 1;
        svP = (svP == 2) ? 0 : svP + 1;
    }

    // ---- drain: PV_{qt} ----
    pv_accum(oA, ap, hb + 24576 + (uint32_t)svP * 8192, rB, uB, swB);

    const float inv0 = 1.f / l0r, inv1 = 1.f / l1r;
    const size_t out0 = ((size_t)b * TT + qt * 64 + wh * 16 + gid) * DD;
    const size_t out1 = out0 + 8 * DD;
#pragma unroll
    for (int nd = 0; nd < 8; nd++) {
        const int d0 = nd * 8 + 2 * tig;
        *(float2*)&out[out0 + d0] = make_float2(oA[nd][0] * inv0, oA[nd][1] * inv0);
        *(float2*)&out[out1 + d0] = make_float2(oA[nd][2] * inv1, oA[nd][3] * inv1);
    }
}

// ---------------------------------------------------------------------------
extern "C" void kernel_launch(void* const* d_in, const int* in_sizes, int n_in,
                              void* d_out, int out_size)
{
    const float* X  = (const float*)d_in[0];
    const float* Wq = (const float*)d_in[1];
    const float* bq = (const float*)d_in[2];
    const float* Wk = (const float*)d_in[3];
    const float* bk = (const float*)d_in[4];
    const float* Wv = (const float*)d_in[5];
    const float* bv = (const float*)d_in[6];
    float* out = (float*)d_out;

    prep<<<8192 + 16, 256>>>(X, Wq, Wk, Wv);

    cudaFuncSetAttribute(qkv_mma, cudaFuncAttributeMaxDynamicSharedMemorySize, QKV_SMEM);
    qkv_mma<<<MM / 64, 256, QKV_SMEM>>>(bq, bk, bv);

    cudaFuncSetAttribute(attn_mma, cudaFuncAttributeMaxDynamicSharedMemorySize, ATTN_SMEM);
    attn_mma<<<dim3(32, BB), 256, ATTN_SMEM>>>(out);
}

// round 17
// speedup vs baseline: 1.2356x; 1.1602x over previous
#include <cuda_runtime.h>
#include <cuda_bf16.h>
#include <cuda_fp16.h>
#include <cstdint>
#include <math.h>

#define BB 4
#define TT 4096
#define EE 1024
#define DD 64
#define MM (BB*TT)

// ---------------------------------------------------------------------------
// Device scratch.  Q, K: single fp16. V: single fp16, transposed.
// ---------------------------------------------------------------------------
__device__ __half g_qh [MM*DD];
__device__ __half g_kh [MM*DD];
__device__ __half g_vth[MM*DD];

#define WCHUNK_BYTES (192*128)
__device__ unsigned char g_wh[16*WCHUNK_BYTES];
__device__ unsigned char g_xh[(size_t)MM*16*128];

// ---------------------------------------------------------------------------
// Helpers
// ---------------------------------------------------------------------------
#define DEVINL __device__ __forceinline__

DEVINL uint32_t smem_u32(const void* p) {
    uint32_t a;
    asm("{ .reg .u64 t; cvta.to.shared.u64 t, %1; cvt.u32.u64 %0, t; }"
        : "=r"(a) : "l"(p));
    return a;
}

#define SWZ128(o) ((o) ^ (((o) >> 3) & 0x70))

#define CP_ASYNC16(dst, src) \
    asm volatile("cp.async.cg.shared.global [%0], [%1], 16;" \
                 :: "r"(dst), "l"(src) : "memory")
#define CP_COMMIT() asm volatile("cp.async.commit_group;" ::: "memory")
#define CP_WAIT0()  asm volatile("cp.async.wait_group 0;"  ::: "memory")

#define NB_SYNC(id) asm volatile("bar.sync %0, 128;" :: "r"(id) : "memory")

DEVINL uint32_t pack_h2(__half a, __half b) {
    return (uint32_t)__half_as_ushort(a) |
           ((uint32_t)__half_as_ushort(b) << 16);
}

DEVINL void ldsm_x4(uint32_t r[4], uint32_t addr) {
    asm volatile("ldmatrix.sync.aligned.m8n8.x4.shared.b16 {%0,%1,%2,%3}, [%4];"
        : "=r"(r[0]), "=r"(r[1]), "=r"(r[2]), "=r"(r[3]) : "r"(addr));
}
DEVINL void ldsm_x2(uint32_t r[2], uint32_t addr) {
    asm volatile("ldmatrix.sync.aligned.m8n8.x2.shared.b16 {%0,%1}, [%2];"
        : "=r"(r[0]), "=r"(r[1]) : "r"(addr));
}
DEVINL void mma16816h(float c[4], const uint32_t a[4], const uint32_t b[2]) {
    asm volatile(
        "mma.sync.aligned.m16n8k16.row.col.f32.f16.f16.f32 "
        "{%0,%1,%2,%3}, {%4,%5,%6,%7}, {%8,%9}, {%0,%1,%2,%3};"
        : "+f"(c[0]), "+f"(c[1]), "+f"(c[2]), "+f"(c[3])
        : "r"(a[0]), "r"(a[1]), "r"(a[2]), "r"(a[3]), "r"(b[0]), "r"(b[1]));
}

// ---------------------------------------------------------------------------
// Merged prep (R12, verified)
// ---------------------------------------------------------------------------
__global__ __launch_bounds__(256) void prep(
    const float* __restrict__ X,
    const float* __restrict__ Wq, const float* __restrict__ Wk,
    const float* __restrict__ Wv)
{
    if (blockIdx.x < 8192) {
        const int u = blockIdx.x * 256 + threadIdx.x;
        const int row  = u >> 7;
        const int unit = u & 127;
        const int c    = unit >> 3;
        const int col8 = unit & 7;
        const float4 a = *(const float4*)&X[(size_t)row * EE + c * 64 + col8 * 8];
        const float4 b = *(const float4*)&X[(size_t)row * EE + c * 64 + col8 * 8 + 4];
        uint4 hh = make_uint4(
            pack_h2(__float2half_rn(a.x), __float2half_rn(a.y)),
            pack_h2(__float2half_rn(a.z), __float2half_rn(a.w)),
            pack_h2(__float2half_rn(b.x), __float2half_rn(b.y)),
            pack_h2(__float2half_rn(b.z), __float2half_rn(b.w)));
        size_t off = (((size_t)row * 16 + c) << 7)
                   + ((((uint32_t)col8 * 16) ^ ((uint32_t)(row & 7) << 4)));
        *(uint4*)(g_xh + off) = hh;
    } else {
        const int c = blockIdx.x - 8192;
        for (int it = threadIdx.x; it < 1536; it += 256) {
            int n = it % 192;
            int g = it / 192;
            int mat = n >> 6, d = n & 63;
            const float* Wm = (mat == 0) ? Wq : (mat == 1) ? Wk : Wv;
            int kk0 = g * 8;
            uint32_t hi[4];
#pragma unroll
            for (int j = 0; j < 4; j++) {
                __half h0 = __float2half_rn(Wm[(size_t)(c*64 + kk0 + 2*j    ) * 64 + d]);
                __half h1 = __float2half_rn(Wm[(size_t)(c*64 + kk0 + 2*j + 1) * 64 + d]);
                hi[j] = pack_h2(h0, h1);
            }
            uint32_t sw = SWZ128((uint32_t)n * 128 + (uint32_t)kk0 * 2);
            *(uint4*)(g_wh + (size_t)c * WCHUNK_BYTES + sw) = make_uint4(hi[0], hi[1], hi[2], hi[3]);
        }
    }
}

// ---------------------------------------------------------------------------
// QKV via mma.sync, pure fp16 (R12, verified)
// ---------------------------------------------------------------------------
#define QB_A    0
#define QB_B    8192
#define QB_STRIDE 32768
#define QKV_SMEM (2*QB_STRIDE)   // 65536

__global__ __launch_bounds__(256, 1) void qkv_mma(
    const float* __restrict__ bq, const float* __restrict__ bk,
    const float* __restrict__ bv)
{
    extern __shared__ __align__(1024) unsigned char sm[];
    const uint32_t sb = smem_u32(sm);
    const int tid  = threadIdx.x;
    const int warp = tid >> 5;
    const int lane = tid & 31;
    const int m0   = blockIdx.x * 64;
    const int wbase = warp * 24;

    const int rA = (lane & 7) | (((lane >> 3) & 1) << 3);
    const int uA = lane >> 4;
    const int rB = lane & 7;
    const int uB = (lane >> 3) & 1;
    const uint32_t swA = (uint32_t)(rA & 7) << 4;
    const uint32_t swB = (uint32_t)(rB & 7) << 4;

    float acc[4][3][4];
#pragma unroll
    for (int mt = 0; mt < 4; mt++)
#pragma unroll
        for (int nt = 0; nt < 3; nt++)
#pragma unroll
            for (int i = 0; i < 4; i++) acc[mt][nt][i] = 0.f;

    {
#pragma unroll
        for (int j = 0; j < 6; j++) {
            int f = tid + 256 * j;
            CP_ASYNC16(sb + QB_B + f * 16, g_wh + (size_t)f * 16);
        }
#pragma unroll
        for (int i = 0; i < 2; i++) {
            int w = tid + 256 * i;
            size_t src = (((size_t)(m0 + (w >> 3)) * 16) << 7) + (w & 7) * 16;
            CP_ASYNC16(sb + QB_A + (uint32_t)w * 16, g_xh + src);
        }
        CP_COMMIT();
        CP_WAIT0();
        __syncthreads();
    }

    for (int c = 0; c < 16; c++) {
        const uint32_t bufc = sb + (uint32_t)(c & 1) * QB_STRIDE;
        const uint32_t bufn = sb + (uint32_t)((c + 1) & 1) * QB_STRIDE;
        const bool hasNext = (c < 15);

        if (hasNext) {
            const unsigned char* wh = g_wh + (size_t)(c + 1) * WCHUNK_BYTES;
#pragma unroll
            for (int j = 0; j < 6; j++) {
                int f = tid + 256 * j;
                CP_ASYNC16(bufn + QB_B + f * 16, wh + (size_t)f * 16);
            }
#pragma unroll
            for (int i = 0; i < 2; i++) {
                int w = tid + 256 * i;
                size_t src = (((size_t)(m0 + (w >> 3)) * 16 + (c + 1)) << 7) + (w & 7) * 16;
                CP_ASYNC16(bufn + QB_A + (uint32_t)w * 16, g_xh + src);
            }
            CP_COMMIT();
        }

#pragma unroll
        for (int kk = 0; kk < 4; kk++) {
            uint32_t ah[4][4];
#pragma unroll
            for (int mt = 0; mt < 4; mt++) {
                uint32_t ra = bufc + QB_A + (uint32_t)(16*mt + rA) * 128
                            + (((uint32_t)(2*kk + uA) * 16) ^ swA);
                ldsm_x4(ah[mt], ra);
            }
            uint32_t bh[3][2];
#pragma unroll
            for (int nt = 0; nt < 3; nt++) {
                uint32_t rb = bufc + QB_B + (uint32_t)(wbase + 8*nt + rB) * 128
                            + (((uint32_t)(2*kk + uB) * 16) ^ swB);
                ldsm_x2(bh[nt], rb);
            }
#pragma unroll
            for (int mt = 0; mt < 4; mt++)
#pragma unroll
                for (int nt = 0; nt < 3; nt++)
                    mma16816h(acc[mt][nt], ah[mt], bh[nt]);
        }

        CP_WAIT0();
        __syncthreads();
    }

    const int gid = lane >> 2, tig = lane & 3;
#pragma unroll
    for (int mt = 0; mt < 4; mt++) {
#pragma unroll
        for (int nt = 0; nt < 3; nt++) {
            const int col0 = wbase + 8 * nt;
            const int mat  = col0 >> 6;
            const int d0   = (col0 & 63) + 2 * tig;
            const float* bp = (mat == 0) ? bq : (mat == 1) ? bk : bv;
            const float b0v = bp[d0], b1v = bp[d0 + 1];
            const int row0 = m0 + 16 * mt + gid;
            float v00 = acc[mt][nt][0] + b0v, v01 = acc[mt][nt][1] + b1v;
            float v10 = acc[mt][nt][2] + b0v, v11 = acc[mt][nt][3] + b1v;
            if (mat == 0) {
                v00 *= 0.125f; v01 *= 0.125f; v10 *= 0.125f; v11 *= 0.125f;
                *(uint32_t*)&g_qh[(size_t)row0 * DD + d0] =
                    pack_h2(__float2half_rn(v00), __float2half_rn(v01));
                *(uint32_t*)&g_qh[(size_t)(row0 + 8) * DD + d0] =
                    pack_h2(__float2half_rn(v10), __float2half_rn(v11));
            } else if (mat == 1) {
                *(uint32_t*)&g_kh[(size_t)row0 * DD + d0] =
                    pack_h2(__float2half_rn(v00), __float2half_rn(v01));
                *(uint32_t*)&g_kh[(size_t)(row0 + 8) * DD + d0] =
                    pack_h2(__float2half_rn(v10), __float2half_rn(v11));
            } else {
                const int bb = row0 >> 12, t = row0 & 4095;
                size_t r0o = ((size_t)bb * 64 + d0) * TT + t;
                size_t r1o = ((size_t)bb * 64 + d0 + 1) * TT + t;
                g_vth[r0o]     = __float2half_rn(v00);
                g_vth[r1o]     = __float2half_rn(v01);
                g_vth[r0o + 8] = __float2half_rn(v10);
                g_vth[r1o + 8] = __float2half_rn(v11);
            }
        }
    }
}

// ---------------------------------------------------------------------------
// Flash attention, pure fp16, kv-tile 128 (halved per-iteration overhead).
// Paired halves: constant 33 kv-128 tiles per CTA. Double-buffered K/V.
// Per half: Q 8K @0, K @8192 (2x16K), V @40960 (2x16K, each as two 64-token
// sub-tiles of 8K) = 72K. Grid (32, B).
// ---------------------------------------------------------------------------
#define AH_STRIDE 73728
#define ATTN_SMEM (2*AH_STRIDE)   // 147456

DEVINL void stage_k128(uint32_t dst, int htid, int b, int t0) {
#pragma unroll
    for (int i = 0; i < 8; i++) {
        int u = htid + 128 * i;                // 0..1023
        int r = u >> 3, cu = u & 7;            // r: token 0..127
        const __half* src = g_kh + (size_t)(b * TT + t0 + r) * DD + cu * 8;
        uint32_t d = dst + (uint32_t)r * 128
                   + (((uint32_t)cu * 16) ^ ((uint32_t)(r & 7) << 4));
        CP_ASYNC16(d, src);
    }
}
DEVINL void stage_v128(uint32_t dst, int htid, int b, int t0) {
#pragma unroll
    for (int i = 0; i < 8; i++) {
        int u = htid + 128 * i;                // 0..1023
        int sub = u >> 9, w = u & 511;         // sub-tile of 64 tokens
        int r = w >> 3, cu = w & 7;            // r: d 0..63
        const __half* src = g_vth + ((size_t)b * DD + r) * TT + t0 + sub * 64 + cu * 8;
        uint32_t d = dst + (uint32_t)sub * 8192 + (uint32_t)r * 128
                   + (((uint32_t)cu * 16) ^ ((uint32_t)(r & 7) << 4));
        CP_ASYNC16(d, src);
    }
}

__global__ __launch_bounds__(256, 1) void attn_mma(float* __restrict__ out)
{
    extern __shared__ __align__(1024) unsigned char sm[];
    const uint32_t sb = smem_u32(sm);
    const int tid  = threadIdx.x;
    const int warp = tid >> 5;
    const int lane = tid & 31;
    const int half = warp >> 2;
    const int wh   = warp & 3;
    const int htid = tid & 127;
    const int b    = blockIdx.y;
    const int qp   = blockIdx.x;
    const int qt   = half ? (63 - qp) : qp;
    const uint32_t hb = sb + (uint32_t)half * AH_STRIDE;
    const int tok0 = b * TT + qt * 64;
    const int nbid = half + 1;
    const int jt   = qt >> 1;    // last kv-128 tile index

    const int gid = lane >> 2, tig = lane & 3;
    const int rA = (lane & 7) | (((lane >> 3) & 1) << 3);
    const int uA = lane >> 4;
    const int rB = lane & 7;
    const int uB = (lane >> 3) & 1;
    const uint32_t swA = (uint32_t)(rA & 7) << 4;
    const uint32_t swB = (uint32_t)(rB) << 4;

    // ---- stage Q + KV tile 0 ----
#pragma unroll
    for (int i = 0; i < 4; i++) {
        int u = htid + 128 * i;
        int r = u >> 3, cu = u & 7;
        const __half* src = g_qh + (size_t)(tok0 + r) * DD + cu * 8;
        uint32_t dst = hb + (uint32_t)r * 128
                     + (((uint32_t)cu * 16) ^ ((uint32_t)(r & 7) << 4));
        CP_ASYNC16(dst, src);
    }
    stage_k128(hb + 8192,  htid, b, 0);
    stage_v128(hb + 40960, htid, b, 0);
    CP_COMMIT();
    CP_WAIT0();
    NB_SYNC(nbid);

    uint32_t qh[4][4];
#pragma unroll
    for (int kk = 0; kk < 4; kk++) {
        uint32_t ra = hb + (uint32_t)(wh * 16 + rA) * 128
                    + (((uint32_t)(2*kk + uA) * 16) ^ swA);
        ldsm_x4(qh[kk], ra);
    }

    float oA[8][4];
#pragma unroll
    for (int nd = 0; nd < 8; nd++)
#pragma unroll
        for (int i = 0; i < 4; i++) oA[nd][i] = 0.f;
    float m0r = -3.0e38f, m1r = -3.0e38f, l0r = 0.f, l1r = 0.f;

    for (int j = 0; j <= jt; j++) {
        if (j) { CP_WAIT0(); NB_SYNC(nbid); }
        const uint32_t kbase = hb + 8192  + (uint32_t)(j & 1) * 16384;
        const uint32_t vbase = hb + 40960 + (uint32_t)(j & 1) * 16384;

        if (j < jt) {
            stage_k128(hb + 8192  + (uint32_t)((j + 1) & 1) * 16384, htid, b, (j + 1) * 128);
            stage_v128(hb + 40960 + (uint32_t)((j + 1) & 1) * 16384, htid, b, (j + 1) * 128);
            CP_COMMIT();
        }

        // ---- S = Q . K^T over 128 tokens (16 n-tiles) ----
        float sA[16][4];
#pragma unroll
        for (int nt = 0; nt < 16; nt++)
#pragma unroll
            for (int i = 0; i < 4; i++) sA[nt][i] = 0.f;
#pragma unroll
        for (int kk = 0; kk < 4; kk++) {
            uint32_t bh[16][2];
#pragma unroll
            for (int nt = 0; nt < 16; nt++) {
                uint32_t rb = kbase + (uint32_t)(nt * 8 + rB) * 128
                            + (((uint32_t)(2*kk + uB) * 16) ^ swB);
                ldsm_x2(bh[nt], rb);
            }
#pragma unroll
            for (int nt = 0; nt < 16; nt++) mma16816h(sA[nt], qh[kk], bh[nt]);
        }

        // ---- causal mask (last tile only; scale folded into q) ----
        if (j == jt) {
            const int r0 = qt * 64 + wh * 16 + gid, r1 = r0 + 8;
#pragma unroll
            for (int nt = 0; nt < 16; nt++) {
                int c0 = j * 128 + nt * 8 + 2 * tig;
                if (c0     > r0) sA[nt][0] = -1e30f;
                if (c0 + 1 > r0) sA[nt][1] = -1e30f;
                if (c0     > r1) sA[nt][2] = -1e30f;
                if (c0 + 1 > r1) sA[nt][3] = -1e30f;
            }
        }

        // ---- online softmax ----
        float mx0 = sA[0][0], mx1 = sA[0][2];
#pragma unroll
        for (int nt = 0; nt < 16; nt++) {
            mx0 = fmaxf(mx0, fmaxf(sA[nt][0], sA[nt][1]));
            mx1 = fmaxf(mx1, fmaxf(sA[nt][2], sA[nt][3]));
        }
        mx0 = fmaxf(mx0, __shfl_xor_sync(0xffffffffu, mx0, 1));
        mx0 = fmaxf(mx0, __shfl_xor_sync(0xffffffffu, mx0, 2));
        mx1 = fmaxf(mx1, __shfl_xor_sync(0xffffffffu, mx1, 1));
        mx1 = fmaxf(mx1, __shfl_xor_sync(0xffffffffu, mx1, 2));
        float mn0 = fmaxf(m0r, mx0), mn1 = fmaxf(m1r, mx1);
        float al0 = __expf(m0r - mn0), al1 = __expf(m1r - mn1);
        float ps0 = 0.f, ps1 = 0.f;
#pragma unroll
        for (int nt = 0; nt < 16; nt++) {
            sA[nt][0] = __expf(sA[nt][0] - mn0);
            sA[nt][1] = __expf(sA[nt][1] - mn0);
            sA[nt][2] = __expf(sA[nt][2] - mn1);
            sA[nt][3] = __expf(sA[nt][3] - mn1);
            ps0 += sA[nt][0] + sA[nt][1];
            ps1 += sA[nt][2] + sA[nt][3];
        }
        ps0 += __shfl_xor_sync(0xffffffffu, ps0, 1);
        ps0 += __shfl_xor_sync(0xffffffffu, ps0, 2);
        ps1 += __shfl_xor_sync(0xffffffffu, ps1, 1);
        ps1 += __shfl_xor_sync(0xffffffffu, ps1, 2);
        l0r = l0r * al0 + ps0;  m0r = mn0;
        l1r = l1r * al1 + ps1;  m1r = mn1;
#pragma unroll
        for (int nd = 0; nd < 8; nd++) {
            oA[nd][0] *= al0; oA[nd][1] *= al0;
            oA[nd][2] *= al1; oA[nd][3] *= al1;
        }

        // ---- PV: O += round16(P) . Vh  (8 k-steps over 128 tokens) ----
#pragma unroll
        for (int kk = 0; kk < 8; kk++) {
            uint32_t ap[4];
            ap[0] = pack_h2(__float2half_rn(sA[2*kk][0]),   __float2half_rn(sA[2*kk][1]));
            ap[1] = pack_h2(__float2half_rn(sA[2*kk][2]),   __float2half_rn(sA[2*kk][3]));
            ap[2] = pack_h2(__float2half_rn(sA[2*kk+1][0]), __float2half_rn(sA[2*kk+1][1]));
            ap[3] = pack_h2(__float2half_rn(sA[2*kk+1][2]), __float2half_rn(sA[2*kk+1][3]));
            const uint32_t vsub = vbase + (uint32_t)(kk >> 2) * 8192;
            const int kks = kk & 3;
            uint32_t vh[8][2];
#pragma unroll
            for (int nd = 0; nd < 8; nd++) {
                uint32_t rv = vsub + (uint32_t)(nd * 8 + rB) * 128
                            + (((uint32_t)(2*kks + uB) * 16) ^ swB);
                ldsm_x2(vh[nd], rv);
            }
#pragma unroll
            for (int nd = 0; nd < 8; nd++) mma16816h(oA[nd], ap, vh[nd]);
        }
    }

    const float inv0 = 1.f / l0r, inv1 = 1.f / l1r;
    const size_t out0 = ((size_t)b * TT + qt * 64 + wh * 16 + gid) * DD;
    const size_t out1 = out0 + 8 * DD;
#pragma unroll
    for (int nd = 0; nd < 8; nd++) {
        const int d0 = nd * 8 + 2 * tig;
        *(float2*)&out[out0 + d0] = make_float2(oA[nd][0] * inv0, oA[nd][1] * inv0);
        *(float2*)&out[out1 + d0] = make_float2(oA[nd][2] * inv1, oA[nd][3] * inv1);
    }
}

// ---------------------------------------------------------------------------
extern "C" void kernel_launch(void* const* d_in, const int* in_sizes, int n_in,
                              void* d_out, int out_size)
{
    const float* X  = (const float*)d_in[0];
    const float* Wq = (const float*)d_in[1];
    const float* bq = (const float*)d_in[2];
    const float* Wk = (const float*)d_in[3];
    const float* bk = (const float*)d_in[4];
    const float* Wv = (const float*)d_in[5];
    const float* bv = (const float*)d_in[6];
    float* out = (float*)d_out;

    prep<<<8192 + 16, 256>>>(X, Wq, Wk, Wv);

    cudaFuncSetAttribute(qkv_mma, cudaFuncAttributeMaxDynamicSharedMemorySize, QKV_SMEM);
    qkv_mma<<<MM / 64, 256, QKV_SMEM>>>(bq, bk, bv);

    cudaFuncSetAttribute(attn_mma, cudaFuncAttributeMaxDynamicSharedMemorySize, ATTN_SMEM);
    attn_mma<<<dim3(32, BB), 256, ATTN_SMEM>>>(out);
}